// round 13
// baseline (speedup 1.0000x reference)
#include <cuda_runtime.h>

#define N 256
#define T 512
#define GRID 256         // 1 anchor per block, 2 blocks co-resident per SM
#define PROW 36          // padded partials row stride (floats): 144B, 16B-aligned

// Scratch (allocations forbidden)
__device__ float2   g_part[GRID];
__device__ unsigned g_count = 0;

__global__ void __launch_bounds__(T, 2)
fused_kernel(const int* __restrict__ raw,
             const float* __restrict__ emb,
             float* __restrict__ out) {
    __shared__ float s_p[N * PROW];            // partials[row][lane], ~36.9KB
    __shared__ float s_dn[N];                  // masked distances
    __shared__ int   s_lab[N];
    __shared__ float s_wmax[8];
    __shared__ int   s_cnt[8];
    __shared__ float s_ed[N];                  // compacted positive distances
    __shared__ float s_val[N];

    const int t    = threadIdx.x;
    const int lane = t & 31;
    const int w    = t >> 5;                   // 16 warps
    const int i    = blockIdx.x;               // anchor index

    // --- Anchor row first: coalesced LDG.128, same addr across warps ---
    const float4* e4 = reinterpret_cast<const float4*>(emb);
    const float4 a = __ldg(e4 + i * 32 + lane);

    // --- Warp-local label decode (warps 0-7; no block barrier needed).
    //     Probe odd words within the FIRST 256 int32 words only (in-bounds
    //     for both layouts): int64 -> zero high-words; int32 -> random 0..15,
    //     P(32 zeros) = 16^-32 ~ 0. Deterministic either way.
    if (w < 8) {
        const int k = t;                       // 0..255
        int probe = raw[2 * (t & 127) + 1];
        int is64 = !__any_sync(0xffffffffu, probe != 0);
        s_lab[k] = is64 ? raw[2 * k] : raw[k];
    }

    // --- Dot phase: warp w owns rows w+16j; lanes store contiguous [row][lane] ---
    // d^2 = sum (a_i - a_k)^2 ; per-lane partial over 4 columns
#pragma unroll
    for (int j = 0; j < 16; j++) {
        const int row = w + 16 * j;
        float4 x = __ldg(e4 + row * 32 + lane);      // coalesced 512B per warp
        float dx = x.x - a.x, dy = x.y - a.y, dz = x.z - a.z, dw = x.w - a.w;
        s_p[row * PROW + lane] = dx * dx + dy * dy + dz * dz + dw * dw;
    }
    __syncthreads();                                 // bar A: partials + labels

    // --- Threads 0..255: reduce own row's 32 partials (8x LDS.128, conflict-free:
    //     bank-word = 4(k+q) mod 32, distinct across each 8-lane phase) ---
    float d = 0.f;
    bool pos = false;
    unsigned bp = 0;
    if (t < N) {
        const int k = t;
        const float4* pr = reinterpret_cast<const float4*>(s_p + k * PROW);
        float4 acc0 = pr[0], acc1 = pr[1];
        float4 q2 = pr[2], q3 = pr[3], q4 = pr[4], q5 = pr[5], q6 = pr[6], q7 = pr[7];
        acc0.x += q2.x; acc0.y += q2.y; acc0.z += q2.z; acc0.w += q2.w;
        acc1.x += q3.x; acc1.y += q3.y; acc1.z += q3.z; acc1.w += q3.w;
        acc0.x += q4.x; acc0.y += q4.y; acc0.z += q4.z; acc0.w += q4.w;
        acc1.x += q5.x; acc1.y += q5.y; acc1.z += q5.z; acc1.w += q5.w;
        acc0.x += q6.x; acc0.y += q6.y; acc0.z += q6.z; acc0.w += q6.w;
        acc1.x += q7.x; acc1.y += q7.y; acc1.z += q7.z; acc1.w += q7.w;
        const float s2 = ((acc0.x + acc1.x) + (acc0.y + acc1.y))
                       + ((acc0.z + acc1.z) + (acc0.w + acc1.w));  // fixed order
        // clip(.,0) then clip(.,EPS) == max(.,EPS)
        d = sqrtf(fmaxf(s2, 1e-4f));

        const int  lk  = s_lab[k], li = s_lab[i];
        const bool neg = (lk != li) || (k == i);     // j-set membership
        pos = (lk == li) && (k != i);

        // masked distance (d >= 0.01 > -1, -1 never passes "> d")
        const float dn = neg ? d : -1.f;
        s_dn[k] = dn;

        float mx = dn;
#pragma unroll
        for (int off = 16; off > 0; off >>= 1)       // fixed-order butterfly
            mx = fmaxf(mx, __shfl_xor_sync(0xffffffffu, mx, off));
        bp = __ballot_sync(0xffffffffu, pos);
        if (lane == 0) {
            s_wmax[w] = mx;
            s_cnt[w]  = __popc(bp);
        }
    }
    __syncthreads();                                 // bar B

    // --- Deterministic compaction slots + block maxd + count (all threads) ---
    int C = 0, pfx = 0;
    float maxd = -1.f;
#pragma unroll
    for (int q = 0; q < 8; q++) {
        int c = s_cnt[q];
        if (q < w) pfx += c;
        C += c;
        maxd = fmaxf(maxd, s_wmax[q]);
    }
    if (pos) {
        unsigned lt = (1u << lane) - 1u;
        s_ed[pfx + __popc(bp & lt)] = d;
    }
    __syncthreads();                                 // bar C

    // --- Warp-cooperative successor-min scan; C ~ 15 => one round ---
    const float4* p4 = reinterpret_cast<const float4*>(s_dn);
    for (int e = w; e < C; e += 16) {
        const float dv = s_ed[e];                    // broadcast
        float4 u = p4[lane], v = p4[lane + 32];      // conflict-free LDS.128
        float m = 3.402823466e+38f;
        if (u.x > dv) m = fminf(m, u.x);
        if (u.y > dv) m = fminf(m, u.y);
        if (u.z > dv) m = fminf(m, u.z);
        if (u.w > dv) m = fminf(m, u.w);
        if (v.x > dv) m = fminf(m, v.x);
        if (v.y > dv) m = fminf(m, v.y);
        if (v.z > dv) m = fminf(m, v.z);
        if (v.w > dv) m = fminf(m, v.w);
#pragma unroll
        for (int off = 16; off > 0; off >>= 1)
            m = fminf(m, __shfl_xor_sync(0xffffffffu, m, off));
        if (lane == 0) {
            // mask_final <=> exists d_ij > d_ik <=> maxd > d_ik
            const float semi = (maxd > dv) ? (dv - m) : (dv - maxd);
            s_val[e] = fmaxf(0.f, semi + 1.0f);
        }
    }
    __syncthreads();                                 // bar D

    // --- Warp 0: fixed-order block sum + cross-block handoff ---
    if (t < 32) {
        float sv = 0.f;
        for (int e = lane; e < C; e += 32) sv += s_val[e];
#pragma unroll
        for (int off = 16; off > 0; off >>= 1)
            sv += __shfl_xor_sync(0xffffffffu, sv, off);

        unsigned rank = 0;
        if (lane == 0) {
            g_part[i] = make_float2(sv, (float)C);
            // release-ordered completion count (replaces __threadfence + atomic)
            asm volatile("atom.add.release.gpu.u32 %0, [%1], 1;"
                         : "=r"(rank) : "l"(&g_count) : "memory");
        }
        rank = __shfl_sync(0xffffffffu, rank, 0);

        // --- Last block: deterministic final reduction over 256 partials ---
        if (rank == GRID - 1) {
            float sx = 0.f, sy = 0.f;
#pragma unroll
            for (int q = 0; q < 8; q++) {
                const float2* gp = (const float2*)g_part + lane + q * 32;
                float2 vv;
                asm volatile("ld.global.cg.v2.f32 {%0,%1}, [%2];"
                             : "=f"(vv.x), "=f"(vv.y) : "l"(gp));
                sx += vv.x; sy += vv.y;
            }
#pragma unroll
            for (int off = 16; off > 0; off >>= 1) {
                sx += __shfl_xor_sync(0xffffffffu, sx, off);
                sy += __shfl_xor_sync(0xffffffffu, sy, off);
            }
            if (lane == 0) {
                out[0] = sx / sy;
                g_count = 0;                         // reset for replay
            }
        }
    }
}

extern "C" void kernel_launch(void* const* d_in, const int* in_sizes, int n_in,
                              void* d_out, int out_size) {
    const float* emb = (const float*)d_in[0];
    const int*   lab = (const int*)d_in[1];  // int32 view; kernel autodetects int64
    (void)in_sizes; (void)n_in; (void)out_size;

    fused_kernel<<<GRID, T>>>(lab, emb, (float*)d_out);
}

// round 14
// speedup vs baseline: 1.0182x; 1.0182x over previous
#include <cuda_runtime.h>

#define N 256
#define T 512
#define GRID 256         // 1 anchor per block, 2 blocks co-resident per SM
#define PROW 257         // padded partials stride (floats): [lane][row], R11 layout

// Scratch (allocations forbidden)
__device__ float2   g_part[GRID];
__device__ unsigned g_count = 0;

__global__ void __launch_bounds__(T, 2)
fused_kernel(const int* __restrict__ raw,
             const float* __restrict__ emb,
             float* __restrict__ out) {
    __shared__ float  s_p[32 * PROW];          // partials[lane][row], 32.9KB
    __shared__ float  s_dn[N];                 // masked distances
    __shared__ int    s_lab[N];
    __shared__ float  s_wmax[8];
    __shared__ float2 s_ws[8];                 // per-warp (sum, count)

    const int t    = threadIdx.x;
    const int lane = t & 31;
    const int w    = t >> 5;                   // 16 warps
    const int i    = blockIdx.x;               // anchor index

    // --- Anchor row first: coalesced LDG.128, same addr across warps ---
    const float4* e4 = reinterpret_cast<const float4*>(emb);
    const float4 a = __ldg(e4 + i * 32 + lane);

    // --- Warp-local label decode (warps 0-7; no block barrier needed).
    //     Probe odd words within the FIRST 256 int32 words only (in-bounds
    //     for both layouts): int64 -> zero high-words; int32 -> random 0..15,
    //     P(32 zeros) = 16^-32 ~ 0. Deterministic either way.
    if (w < 8) {
        const int k = t;                       // 0..255
        int probe = raw[2 * (t & 127) + 1];
        int is64 = !__any_sync(0xffffffffu, probe != 0);
        s_lab[k] = is64 ? raw[2 * k] : raw[k];
    }

    // --- Dot phase: warp w owns rows w+16j (R11 layout) ---
    // d^2 = sum (a_i - a_k)^2 ; per-lane partial over 4 columns
#pragma unroll
    for (int j = 0; j < 16; j++) {
        const int row = w + 16 * j;
        float4 x = __ldg(e4 + row * 32 + lane);      // coalesced 512B per warp
        float dx = x.x - a.x, dy = x.y - a.y, dz = x.z - a.z, dw = x.w - a.w;
        s_p[lane * PROW + row] = dx * dx + dy * dy + dz * dz + dw * dw;
    }
    __syncthreads();                                 // bar A: partials + labels

    // --- Threads 0..255: transpose-reduce 32 partials for row k (R11) ---
    float d = 0.f;
    unsigned bp = 0;
    if (t < N) {
        const int k = t;
        float ax = 0.f, bx = 0.f, cx = 0.f, dx4 = 0.f;
#pragma unroll
        for (int l = 0; l < 32; l += 4) {            // conflict-free LDS.32
            ax  += s_p[(l + 0) * PROW + k];
            bx  += s_p[(l + 1) * PROW + k];
            cx  += s_p[(l + 2) * PROW + k];
            dx4 += s_p[(l + 3) * PROW + k];
        }
        const float s2 = (ax + bx) + (cx + dx4);     // fixed combine order
        // clip(.,0) then clip(.,EPS) == max(.,EPS)
        d = sqrtf(fmaxf(s2, 1e-4f));

        const int  lk  = s_lab[k], li = s_lab[i];
        const bool neg = (lk != li) || (k == i);     // j-set membership
        const bool pos = (lk == li) && (k != i);

        // masked distance (d >= 0.01 > -1, -1 never passes "> d")
        const float dn = neg ? d : -1.f;
        s_dn[k] = dn;

        float mx = dn;
#pragma unroll
        for (int off = 16; off > 0; off >>= 1)       // fixed-order butterfly
            mx = fmaxf(mx, __shfl_xor_sync(0xffffffffu, mx, off));
        bp = __ballot_sync(0xffffffffu, pos);
        if (lane == 0) s_wmax[w] = mx;
    }
    __syncthreads();                                 // bar B: dn + wmax ready

    // --- Warps 0-7: scan own positive lanes (ballot-iterated, fixed order) ---
    if (w < 8) {
        // block maxd (8 broadcast LDS + 7 max)
        float maxd = fmaxf(fmaxf(fmaxf(s_wmax[0], s_wmax[1]),
                                 fmaxf(s_wmax[2], s_wmax[3])),
                           fmaxf(fmaxf(s_wmax[4], s_wmax[5]),
                                 fmaxf(s_wmax[6], s_wmax[7])));
        // hoisted scan operands: each lane holds 8 of the 256 dn values
        const float4* p4 = reinterpret_cast<const float4*>(s_dn);
        const float4 u = p4[lane], v = p4[lane + 32];    // conflict-free LDS.128

        float wsum = 0.f;
        unsigned rem = bp;                                // warp-uniform
        while (rem) {
            const int src = __ffs(rem) - 1;               // ascending -> fixed order
            rem &= rem - 1u;
            const float dv = __shfl_sync(0xffffffffu, d, src);
            float m = 3.402823466e+38f;
            if (u.x > dv) m = fminf(m, u.x);
            if (u.y > dv) m = fminf(m, u.y);
            if (u.z > dv) m = fminf(m, u.z);
            if (u.w > dv) m = fminf(m, u.w);
            if (v.x > dv) m = fminf(m, v.x);
            if (v.y > dv) m = fminf(m, v.y);
            if (v.z > dv) m = fminf(m, v.z);
            if (v.w > dv) m = fminf(m, v.w);
#pragma unroll
            for (int off = 16; off > 0; off >>= 1)
                m = fminf(m, __shfl_xor_sync(0xffffffffu, m, off));
            // mask_final <=> exists d_ij > d_ik <=> maxd > d_ik
            const float semi = (maxd > dv) ? (dv - m) : (dv - maxd);
            wsum += fmaxf(0.f, semi + 1.0f);              // uniform across lanes
        }
        if (lane == 0) s_ws[w] = make_float2(wsum, (float)__popc(bp));
    }
    __syncthreads();                                      // bar C: warp sums ready

    // --- Warp 0: combine 8 warp sums + cross-block handoff ---
    if (t < 32) {
        float2 r = (lane < 8) ? s_ws[lane] : make_float2(0.f, 0.f);
#pragma unroll
        for (int off = 4; off > 0; off >>= 1) {           // fixed-order reduce over 8
            r.x += __shfl_xor_sync(0xffffffffu, r.x, off);
            r.y += __shfl_xor_sync(0xffffffffu, r.y, off);
        }

        unsigned rank = 0;
        if (lane == 0) {
            g_part[i] = make_float2(r.x, r.y);
            // acq_rel completion count: release publishes g_part[i]; the
            // winning (last) block's acquire orders its g_part reads below.
            asm volatile("atom.add.acq_rel.gpu.u32 %0, [%1], 1;"
                         : "=r"(rank) : "l"(&g_count) : "memory");
        }
        rank = __shfl_sync(0xffffffffu, rank, 0);

        // --- Last block: deterministic final reduction over 256 partials ---
        if (rank == GRID - 1) {
            float sx = 0.f, sy = 0.f;
#pragma unroll
            for (int q = 0; q < 8; q++) {
                const float2* gp = (const float2*)g_part + lane + q * 32;
                float2 vv;
                asm volatile("ld.global.cg.v2.f32 {%0,%1}, [%2];"
                             : "=f"(vv.x), "=f"(vv.y) : "l"(gp));
                sx += vv.x; sy += vv.y;
            }
#pragma unroll
            for (int off = 16; off > 0; off >>= 1) {
                sx += __shfl_xor_sync(0xffffffffu, sx, off);
                sy += __shfl_xor_sync(0xffffffffu, sy, off);
            }
            if (lane == 0) {
                out[0] = sx / sy;
                g_count = 0;                              // reset for replay
            }
        }
    }
}

extern "C" void kernel_launch(void* const* d_in, const int* in_sizes, int n_in,
                              void* d_out, int out_size) {
    const float* emb = (const float*)d_in[0];
    const int*   lab = (const int*)d_in[1];  // int32 view; kernel autodetects int64
    (void)in_sizes; (void)n_in; (void)out_size;

    fused_kernel<<<GRID, T>>>(lab, emb, (float*)d_out);
}